// round 2
// baseline (speedup 1.0000x reference)
#include <cuda_runtime.h>
#include <math.h>

// ---------------------------------------------------------------------------
// WriteAngleParameters: triplet gather + MLP (fp32, f32x2-packed FMA)
// Register tile: 8 triplets x 8 cols per thread. 256 threads, TILE=256.
// Gathered x rows staged to smem via cp.async; activations read as LDS.128.
// ---------------------------------------------------------------------------

namespace {

constexpr int REP      = 256;
constexpr int BW       = 64;
constexpr int TILE     = 256;    // triplets per CTA
constexpr int NTHREADS = 256;    // 32 tg x 8 cg
constexpr int R        = 8;      // triplets per thread
constexpr int ZS       = 68;     // padded row stride (floats), 272B = 16B-aligned

constexpr float PI_F   = 3.14159265358979323846f;
constexpr float EQ_STD = 0.1f;
constexpr float K_MEAN = 120.0f;
constexpr float K_STD  = 50.0f;

// smem layout (floats)
constexpr int OFF_A    = 0;                    // x staging / z buffer A: 256*68
constexpr int OFF_B    = OFF_A + TILE * ZS;    // W0 chunk (16384) / z buffer B
constexpr int OFF_WS   = OFF_B + TILE * ZS;
constexpr int OFF_W1   = OFF_WS + BW * BW;
constexpr int OFF_W2   = OFF_W1 + BW * BW;
constexpr int OFF_W3   = OFF_W2 + BW * BW;
constexpr int OFF_W4   = OFF_W3 + BW * BW;     // 128
constexpr int OFF_B0   = OFF_W4 + 128;
constexpr int OFF_B1   = OFF_B0 + 64;
constexpr int OFF_BSC  = OFF_B1 + 64;          // bs + b2 combined
constexpr int OFF_B3   = OFF_BSC + 64;
constexpr int OFF_B4   = OFF_B3 + 64;          // 4
constexpr int OFF_IDX  = OFF_B4 + 4;           // TILE*3 ints
constexpr int SMEM_FLOATS = OFF_IDX + TILE * 3;
constexpr size_t SMEM_BYTES = (size_t)SMEM_FLOATS * sizeof(float);

__device__ __forceinline__ unsigned long long splat2(float x) {
    unsigned long long r;
    asm("mov.b64 %0, {%1, %1};" : "=l"(r) : "f"(x));
    return r;
}
__device__ __forceinline__ float2 unpack2(unsigned long long v) {
    float2 r;
    asm("mov.b64 {%0, %1}, %2;" : "=f"(r.x), "=f"(r.y) : "l"(v));
    return r;
}
#define FMA2(d, a, b) asm("fma.rn.f32x2 %0, %1, %2, %0;" : "+l"(d) : "l"(a), "l"(b))

__device__ __forceinline__ void cp16(float* dst_smem, const float* src) {
    unsigned sdst = (unsigned)__cvta_generic_to_shared(dst_smem);
    asm volatile("cp.async.cg.shared.global [%0], [%1], 16;" :: "r"(sdst), "l"(src));
}
__device__ __forceinline__ void cp_wait_all() {
    asm volatile("cp.async.commit_group;\n\tcp.async.wait_group 0;" ::: "memory");
}

__device__ __forceinline__ float eluf(float x) {
    return x > 0.0f ? x : expm1f(x);
}

// acc[r*4+c] accumulates cols [cg*8 .. cg*8+7] (4 x f32x2) for triplet lt[r].
// sact: activation rows (stride ZS), sw: weight rows (stride 64), 64 k-steps.
__device__ __forceinline__ void mm64(const float* __restrict__ sact,
                                     const float* __restrict__ sw,
                                     unsigned long long acc[R * 4],
                                     const int ltoff[R], int cg8) {
    #pragma unroll 2
    for (int k1 = 0; k1 < 16; k1++) {
        float4 xa[R];
        #pragma unroll
        for (int r = 0; r < R; r++)
            xa[r] = *(const float4*)(sact + ltoff[r] + k1 * 4);
        #pragma unroll
        for (int u = 0; u < 4; u++) {
            const float* wr = sw + (k1 * 4 + u) * BW + cg8;
            ulonglong2 wa = *(const ulonglong2*)wr;
            ulonglong2 wb = *(const ulonglong2*)(wr + 4);
            #pragma unroll
            for (int r = 0; r < R; r++) {
                float xv = u == 0 ? xa[r].x : u == 1 ? xa[r].y : u == 2 ? xa[r].z : xa[r].w;
                unsigned long long s = splat2(xv);
                FMA2(acc[4 * r + 0], wa.x, s);
                FMA2(acc[4 * r + 1], wa.y, s);
                FMA2(acc[4 * r + 2], wb.x, s);
                FMA2(acc[4 * r + 3], wb.y, s);
            }
        }
    }
}

__device__ __forceinline__ void load_bias(const float* sb, int cg8,
                                          unsigned long long acc[R * 4]) {
    const unsigned long long* bp = (const unsigned long long*)(sb + cg8);
    #pragma unroll
    for (int c = 0; c < 4; c++) {
        unsigned long long bv = bp[c];
        #pragma unroll
        for (int r = 0; r < R; r++) acc[4 * r + c] = bv;
    }
}

__device__ __forceinline__ void elu_store(float* dst, const int ltoff[R], int cg8,
                                          const unsigned long long acc[R * 4]) {
    #pragma unroll
    for (int r = 0; r < R; r++) {
        float v[8];
        #pragma unroll
        for (int c = 0; c < 4; c++) {
            float2 p = unpack2(acc[4 * r + c]);
            v[2 * c] = eluf(p.x); v[2 * c + 1] = eluf(p.y);
        }
        *(float4*)(dst + ltoff[r] + cg8)     = make_float4(v[0], v[1], v[2], v[3]);
        *(float4*)(dst + ltoff[r] + cg8 + 4) = make_float4(v[4], v[5], v[6], v[7]);
    }
}

__global__ void __launch_bounds__(NTHREADS, 1)
wap_kernel(const float* __restrict__ h,  const int* __restrict__ idxs,
           const float* __restrict__ W0, const float* __restrict__ b0,
           const float* __restrict__ Ws, const float* __restrict__ bs,
           const float* __restrict__ W1, const float* __restrict__ b1,
           const float* __restrict__ W2, const float* __restrict__ b2,
           const float* __restrict__ W3, const float* __restrict__ b3,
           const float* __restrict__ W4, const float* __restrict__ b4,
           float* __restrict__ out, int nT)
{
    extern __shared__ float smem[];
    float* sA   = smem + OFF_A;
    float* sB   = smem + OFF_B;
    float* sWs  = smem + OFF_WS;
    float* sW1  = smem + OFF_W1;
    float* sW2  = smem + OFF_W2;
    float* sW3  = smem + OFF_W3;
    float* sW4  = smem + OFF_W4;
    float* sb0  = smem + OFF_B0;
    float* sb1  = smem + OFF_B1;
    float* sbsc = smem + OFF_BSC;
    float* sb3  = smem + OFF_B3;
    float* sb4  = smem + OFF_B4;
    int*   sidx = (int*)(smem + OFF_IDX);

    const int tid = threadIdx.x;
    const int cg  = tid & 7;
    const int cg8 = cg * 8;
    const int tg  = tid >> 3;          // 0..31
    const int t0  = blockIdx.x * TILE;

    // ---- stage small weights, biases, indices ----
    for (int i = tid; i < BW * BW; i += NTHREADS) {
        sWs[i] = Ws[i]; sW1[i] = W1[i]; sW2[i] = W2[i]; sW3[i] = W3[i];
    }
    if (tid < 128) sW4[tid] = W4[tid];
    if (tid < 64) {
        sb0[tid] = b0[tid]; sb1[tid] = b1[tid];
        sbsc[tid] = bs[tid] + b2[tid]; sb3[tid] = b3[tid];
    }
    if (tid < 2) sb4[tid] = b4[tid];
    for (int i = tid; i < TILE * 3; i += NTHREADS) {
        int t = t0 + i / 3;
        if (t >= nT) t = nT - 1;       // clamp tail; extra triplets computed, not stored
        sidx[i] = idxs[(size_t)t * 3 + (i % 3)];
    }
    __syncthreads();

    int ltoff[R];
    #pragma unroll
    for (int r = 0; r < R; r++) ltoff[r] = (tg + 32 * r) * ZS;

    // my gather row for staging (thread tid stages triplet tid's data)
    float* myAdst = sA + tid * ZS;

    // ---- layer 0: [768] -> [64] ----
    unsigned long long acc[R * 4];
    load_bias(sb0, cg8, acc);

    for (int n = 0; n < 3; n++) {
        __syncthreads();  // prior chunk's weight reads (B) done
        {   // stage W0 chunk n: rows n*256..n*256+255, 64KB, 64 floats/thread
            const float* src = W0 + (size_t)n * 256 * BW + tid * 64;
            float* dst = sB + tid * 64;
            #pragma unroll
            for (int j = 0; j < 16; j++) cp16(dst + 4 * j, src + 4 * j);
        }
        const float* myrow = h + (size_t)sidx[tid * 3 + n] * REP;

        for (int ks = 0; ks < 4; ks++) {
            if (ks) __syncthreads();   // prior sub-chunk's act reads (A) done
            {   // stage x sub-chunk: 64 floats of my row
                const float* src = myrow + ks * 64;
                #pragma unroll
                for (int j = 0; j < 16; j++) cp16(myAdst + 4 * j, src + 4 * j);
            }
            cp_wait_all();
            __syncthreads();
            mm64(sA, sB + ks * 64 * BW, acc, ltoff, cg8);
        }
    }
    __syncthreads();                   // all act reads done before z0 -> A
    elu_store(sA, ltoff, cg8, acc);
    __syncthreads();                   // z0 (A) ready

    // ---- layer 1: t1 = elu(A@W1 + b1) -> B ----
    load_bias(sb1, cg8, acc);
    mm64(sA, sW1, acc, ltoff, cg8);
    elu_store(sB, ltoff, cg8, acc);
    __syncthreads();                   // z1 (B) ready

    // ---- residual: z = elu(A@Ws + B@W2 + (bs+b2)) -> A ----
    load_bias(sbsc, cg8, acc);
    mm64(sA, sWs, acc, ltoff, cg8);
    mm64(sB, sW2, acc, ltoff, cg8);
    __syncthreads();                   // all reads of A done before overwrite
    elu_store(sA, ltoff, cg8, acc);
    __syncthreads();                   // z2 (A) ready

    // ---- layer 3: z = elu(A@W3 + b3) -> B ----
    load_bias(sb3, cg8, acc);
    mm64(sA, sW3, acc, ltoff, cg8);
    elu_store(sB, ltoff, cg8, acc);
    __syncthreads();                   // final z (B) ready

    // ---- head: one thread per triplet ----
    {
        int t = t0 + tid;
        if (t < nT) {
            const float* zrow = sB + tid * ZS;
            float c0 = sb4[0], c1 = sb4[1];
            #pragma unroll
            for (int k4 = 0; k4 < 16; k4++) {
                float4 z4 = *(const float4*)(zrow + k4 * 4);
                float4 wA = *(const float4*)(sW4 + k4 * 8);
                float4 wB = *(const float4*)(sW4 + k4 * 8 + 4);
                c0 += z4.x * wA.x + z4.y * wA.z + z4.z * wB.x + z4.w * wB.z;
                c1 += z4.x * wA.y + z4.y * wA.w + z4.z * wB.y + z4.w * wB.w;
            }
            float eq = PI_F / (1.0f + expf(-c0 * (EQ_STD / PI_F)));
            float kk = K_STD * eluf(c1 + K_MEAN / K_STD);
            *(float2*)(out + (size_t)t * 2) = make_float2(eq, kk);
        }
    }
}

} // namespace

extern "C" void kernel_launch(void* const* d_in, const int* in_sizes, int n_in,
                              void* d_out, int out_size) {
    const float* h   = (const float*)d_in[0];
    const int*   idx = (const int*)  d_in[1];
    const float* W0  = (const float*)d_in[2];
    const float* b0  = (const float*)d_in[3];
    const float* Ws  = (const float*)d_in[4];
    const float* bs  = (const float*)d_in[5];
    const float* W1  = (const float*)d_in[6];
    const float* b1  = (const float*)d_in[7];
    const float* W2  = (const float*)d_in[8];
    const float* b2  = (const float*)d_in[9];
    const float* W3  = (const float*)d_in[10];
    const float* b3  = (const float*)d_in[11];
    const float* W4  = (const float*)d_in[12];
    const float* b4  = (const float*)d_in[13];
    float* out = (float*)d_out;

    int nT = in_sizes[1] / 3;
    int grid = (nT + TILE - 1) / TILE;

    cudaFuncSetAttribute(wap_kernel,
                         cudaFuncAttributeMaxDynamicSharedMemorySize,
                         (int)SMEM_BYTES);
    wap_kernel<<<grid, NTHREADS, SMEM_BYTES>>>(
        h, idx, W0, b0, Ws, bs, W1, b1, W2, b2, W3, b3, W4, b4, out, nT);
    (void)n_in; (void)out_size;
}

// round 3
// speedup vs baseline: 1.3383x; 1.3383x over previous
#include <cuda_runtime.h>
#include <math.h>

// ---------------------------------------------------------------------------
// WriteAngleParameters: triplet gather + MLP (fp32, packed f32x2 FMA)
// 512 threads = 32 triplet-groups x 16 col-groups. Per thread: 8 triplets x 4 cols.
// Layer-0 x gathered via double-buffered cp.async; small layers warp-local.
// ---------------------------------------------------------------------------

namespace {

constexpr int REP      = 256;
constexpr int BW       = 64;
constexpr int TILE     = 256;
constexpr int NTHREADS = 512;    // tg = tid>>4 (32), cg = tid&15
constexpr int R        = 8;      // triplets per thread (rows tg + 32*r)
constexpr int ZS       = 68;     // padded row stride (floats), 272B

constexpr float PI_F   = 3.14159265358979323846f;
constexpr float EQ_STD = 0.1f;
constexpr float K_MEAN = 120.0f;
constexpr float K_STD  = 50.0f;

// smem layout (floats)
constexpr int OFF_R0   = 0;                      // x buf even / z0 / z2
constexpr int OFF_R1   = OFF_R0 + TILE * ZS;     // x buf odd  / z1 / z3
constexpr int OFF_R2   = OFF_R1 + TILE * ZS;     // W0 chunk (256x64) / small weights
constexpr int OFF_W4   = OFF_R2 + 256 * BW;      // 128
constexpr int OFF_B0   = OFF_W4 + 128;
constexpr int OFF_B1   = OFF_B0 + 64;
constexpr int OFF_BSC  = OFF_B1 + 64;            // bs + b2
constexpr int OFF_B3   = OFF_BSC + 64;
constexpr int OFF_B4   = OFF_B3 + 64;            // 4
constexpr int OFF_IDX  = OFF_B4 + 4;             // TILE*3 ints
constexpr int SMEM_FLOATS = OFF_IDX + TILE * 3;
constexpr size_t SMEM_BYTES = (size_t)SMEM_FLOATS * sizeof(float);

// small-weight offsets inside R2 (after layer 0)
constexpr int WOFF_S = 0, WOFF_1 = 4096, WOFF_2 = 8192, WOFF_3 = 12288;

__device__ __forceinline__ unsigned long long splat2(float x) {
    unsigned long long r;
    asm("mov.b64 %0, {%1, %1};" : "=l"(r) : "f"(x));
    return r;
}
__device__ __forceinline__ float2 unpack2(unsigned long long v) {
    float2 r;
    asm("mov.b64 {%0, %1}, %2;" : "=f"(r.x), "=f"(r.y) : "l"(v));
    return r;
}
#define FMA2(d, a, b) asm("fma.rn.f32x2 %0, %1, %2, %0;" : "+l"(d) : "l"(a), "l"(b))

__device__ __forceinline__ void cp16(float* dst_smem, const float* src) {
    unsigned sdst = (unsigned)__cvta_generic_to_shared(dst_smem);
    asm volatile("cp.async.cg.shared.global [%0], [%1], 16;" :: "r"(sdst), "l"(src));
}
__device__ __forceinline__ void cp_commit() {
    asm volatile("cp.async.commit_group;" ::: "memory");
}
__device__ __forceinline__ void cp_wait1() {
    asm volatile("cp.async.wait_group 1;" ::: "memory");
}
__device__ __forceinline__ void cp_wait0() {
    asm volatile("cp.async.wait_group 0;" ::: "memory");
}

__device__ __forceinline__ float eluf(float x) {
    return x > 0.0f ? x : expm1f(x);
}

// acc[2r],acc[2r+1]: cols cg4..cg4+3 for triplet row (tg + 32r).
// sact rows stride ZS; sw rows stride 64; 64 k-steps.
__device__ __forceinline__ void mm64(const float* __restrict__ sact,
                                     const float* __restrict__ sw,
                                     unsigned long long acc[2 * R],
                                     const int ltoff[R], int cg4) {
    #pragma unroll 2
    for (int k2 = 0; k2 < 32; k2++) {
        float2 xa[R];
        #pragma unroll
        for (int r = 0; r < R; r++)
            xa[r] = *(const float2*)(sact + ltoff[r] + k2 * 2);
        #pragma unroll
        for (int u = 0; u < 2; u++) {
            ulonglong2 w = *(const ulonglong2*)(sw + (k2 * 2 + u) * BW + cg4);
            #pragma unroll
            for (int r = 0; r < R; r++) {
                unsigned long long s = splat2(u == 0 ? xa[r].x : xa[r].y);
                FMA2(acc[2 * r + 0], w.x, s);
                FMA2(acc[2 * r + 1], w.y, s);
            }
        }
    }
}

__device__ __forceinline__ void load_bias(const float* sb, int cg4,
                                          unsigned long long acc[2 * R]) {
    unsigned long long b0 = ((const unsigned long long*)(sb + cg4))[0];
    unsigned long long b1 = ((const unsigned long long*)(sb + cg4))[1];
    #pragma unroll
    for (int r = 0; r < R; r++) { acc[2 * r] = b0; acc[2 * r + 1] = b1; }
}

__device__ __forceinline__ void elu_store(float* dst, const int ltoff[R], int cg4,
                                          const unsigned long long acc[2 * R]) {
    #pragma unroll
    for (int r = 0; r < R; r++) {
        float2 p0 = unpack2(acc[2 * r]);
        float2 p1 = unpack2(acc[2 * r + 1]);
        *(float4*)(dst + ltoff[r] + cg4) =
            make_float4(eluf(p0.x), eluf(p0.y), eluf(p1.x), eluf(p1.y));
    }
}

__global__ void __launch_bounds__(NTHREADS, 1)
wap_kernel(const float* __restrict__ h,  const int* __restrict__ idxs,
           const float* __restrict__ W0, const float* __restrict__ b0,
           const float* __restrict__ Ws, const float* __restrict__ bs,
           const float* __restrict__ W1, const float* __restrict__ b1,
           const float* __restrict__ W2, const float* __restrict__ b2,
           const float* __restrict__ W3, const float* __restrict__ b3,
           const float* __restrict__ W4, const float* __restrict__ b4,
           float* __restrict__ out, int nT)
{
    extern __shared__ float smem[];
    float* sR0  = smem + OFF_R0;
    float* sR1  = smem + OFF_R1;
    float* sR2  = smem + OFF_R2;
    float* sW4  = smem + OFF_W4;
    float* sb0  = smem + OFF_B0;
    float* sb1  = smem + OFF_B1;
    float* sbsc = smem + OFF_BSC;
    float* sb3  = smem + OFF_B3;
    float* sb4  = smem + OFF_B4;
    int*   sidx = (int*)(smem + OFF_IDX);

    const int tid = threadIdx.x;
    const int cg4 = (tid & 15) * 4;
    const int tg  = tid >> 4;          // 0..31
    const int t0  = blockIdx.x * TILE;

    // ---- stage biases, W4, indices (plain loads) ----
    if (tid < 128) sW4[tid] = W4[tid];
    if (tid < 64) {
        sb0[tid] = b0[tid]; sb1[tid] = b1[tid];
        sbsc[tid] = bs[tid] + b2[tid]; sb3[tid] = b3[tid];
    }
    if (tid < 2) sb4[tid] = b4[tid];
    for (int i = tid; i < TILE * 3; i += NTHREADS) {
        int t = t0 + i / 3;
        if (t >= nT) t = nT - 1;       // clamp tail; extras computed, not stored
        sidx[i] = idxs[(size_t)t * 3 + (i % 3)];
    }
    __syncthreads();

    int ltoff[R];
    #pragma unroll
    for (int r = 0; r < R; r++) ltoff[r] = (tg + 32 * r) * ZS;

    float* Xbuf[2] = { sR0, sR1 };
    const int myrowT  = tid >> 1;      // triplet row this thread stages
    const int myhalf  = (tid & 1) * 32;

    // ---- layer 0: [768] -> [64], pipelined cp.async ----
    unsigned long long acc[2 * R];
    load_bias(sb0, cg4, acc);

    // prologue: x(s=0) and W0 chunk 0
    {
        const float* src = h + (size_t)sidx[myrowT * 3 + 0] * REP + myhalf;
        float* dst = Xbuf[0] + myrowT * ZS + myhalf;
        #pragma unroll
        for (int j = 0; j < 8; j++) cp16(dst + 4 * j, src + 4 * j);
        cp_commit();
        const float* wsrc = W0 + tid * 32;
        float* wdst = sR2 + tid * 32;
        #pragma unroll
        for (int j = 0; j < 8; j++) cp16(wdst + 4 * j, wsrc + 4 * j);
        cp_commit();
    }

    for (int s = 0; s < 12; s++) {
        const int n = s >> 2, ks = s & 3;
        __syncthreads();               // readers of Xbuf[(s+1)&1] (mm64 s-1) done
        if (ks == 0 && n > 0) {        // stage W0 chunk n (R2 free: mm64(n-1,3) done)
            const float* wsrc = W0 + (size_t)n * 256 * BW + tid * 32;
            float* wdst = sR2 + tid * 32;
            #pragma unroll
            for (int j = 0; j < 8; j++) cp16(wdst + 4 * j, wsrc + 4 * j);
            cp_commit();
        }
        if (s < 11) {                  // prefetch x(s+1)
            const int n2 = (s + 1) >> 2, ks2 = (s + 1) & 3;
            const float* src = h + (size_t)sidx[myrowT * 3 + n2] * REP + ks2 * 64 + myhalf;
            float* dst = Xbuf[(s + 1) & 1] + myrowT * ZS + myhalf;
            #pragma unroll
            for (int j = 0; j < 8; j++) cp16(dst + 4 * j, src + 4 * j);
            cp_commit();
            cp_wait1();                // x(s) (+ W0(n)) complete; x(s+1) in flight
        } else {
            cp_wait0();
        }
        __syncthreads();               // staged data visible to all
        mm64(Xbuf[s & 1], sR2 + ks * 64 * BW, acc, ltoff, cg4);
    }

    // z0 -> R0 (mm64(11) reads only R1/R2; per-thread cells disjoint)
    elu_store(sR0, ltoff, cg4, acc);
    __syncthreads();                   // all done with R2 (W0) and z0 stores visible

    // ---- stage small weights into R2 ----
    {
        const float* srcs[4] = { Ws, W1, W2, W3 };
        #pragma unroll
        for (int m = 0; m < 4; m++) {
            const float* src = srcs[m] + tid * 8;
            float* dst = sR2 + m * 4096 + tid * 8;
            cp16(dst, src); cp16(dst + 4, src + 4);
        }
        cp_commit(); cp_wait0();
    }
    __syncthreads();

    // ---- small layers: all z-rows are warp-local -> no CTA barriers ----
    // layer 1: z1 = elu(z0 @ W1 + b1) -> R1
    load_bias(sb1, cg4, acc);
    mm64(sR0, sR2 + WOFF_1, acc, ltoff, cg4);
    elu_store(sR1, ltoff, cg4, acc);
    __syncwarp();

    // residual: z2 = elu(z0@Ws + z1@W2 + (bs+b2)) -> R0
    load_bias(sbsc, cg4, acc);
    mm64(sR0, sR2 + WOFF_S, acc, ltoff, cg4);
    mm64(sR1, sR2 + WOFF_2, acc, ltoff, cg4);
    elu_store(sR0, ltoff, cg4, acc);
    __syncwarp();

    // layer 3: z3 = elu(z2 @ W3 + b3) -> R1
    load_bias(sb3, cg4, acc);
    mm64(sR0, sR2 + WOFF_3, acc, ltoff, cg4);
    elu_store(sR1, ltoff, cg4, acc);
    __syncthreads();                   // head reads cross-warp

    // ---- head: threads 0..255, one triplet each ----
    if (tid < TILE) {
        int t = t0 + tid;
        if (t < nT) {
            const float* zrow = sR1 + tid * ZS;
            float c0 = sb4[0], c1 = sb4[1];
            #pragma unroll
            for (int k4 = 0; k4 < 16; k4++) {
                float4 z4 = *(const float4*)(zrow + k4 * 4);
                float4 wA = *(const float4*)(sW4 + k4 * 8);
                float4 wB = *(const float4*)(sW4 + k4 * 8 + 4);
                c0 += z4.x * wA.x + z4.y * wA.z + z4.z * wB.x + z4.w * wB.z;
                c1 += z4.x * wA.y + z4.y * wA.w + z4.z * wB.y + z4.w * wB.w;
            }
            float eq = PI_F / (1.0f + expf(-c0 * (EQ_STD / PI_F)));
            float kk = K_STD * eluf(c1 + K_MEAN / K_STD);
            *(float2*)(out + (size_t)t * 2) = make_float2(eq, kk);
        }
    }
}

} // namespace

extern "C" void kernel_launch(void* const* d_in, const int* in_sizes, int n_in,
                              void* d_out, int out_size) {
    const float* h   = (const float*)d_in[0];
    const int*   idx = (const int*)  d_in[1];
    const float* W0  = (const float*)d_in[2];
    const float* b0  = (const float*)d_in[3];
    const float* Ws  = (const float*)d_in[4];
    const float* bs  = (const float*)d_in[5];
    const float* W1  = (const float*)d_in[6];
    const float* b1  = (const float*)d_in[7];
    const float* W2  = (const float*)d_in[8];
    const float* b2  = (const float*)d_in[9];
    const float* W3  = (const float*)d_in[10];
    const float* b3  = (const float*)d_in[11];
    const float* W4  = (const float*)d_in[12];
    const float* b4  = (const float*)d_in[13];
    float* out = (float*)d_out;

    int nT = in_sizes[1] / 3;
    int grid = (nT + TILE - 1) / TILE;

    cudaFuncSetAttribute(wap_kernel,
                         cudaFuncAttributeMaxDynamicSharedMemorySize,
                         (int)SMEM_BYTES);
    wap_kernel<<<grid, NTHREADS, SMEM_BYTES>>>(
        h, idx, W0, b0, Ws, bs, W1, b1, W2, b2, W3, b3, W4, b4, out, nT);
    (void)n_in; (void)out_size;
}

// round 4
// speedup vs baseline: 1.4693x; 1.0979x over previous
#include <cuda_runtime.h>
#include <math.h>

// ---------------------------------------------------------------------------
// WriteAngleParameters: triplet gather + MLP (fp32, packed f32x2 FMA)
// TILE=128 triplets, 256 threads (16 tg x 16 cg), R=8 triplets x 4 cols/thread.
// 2 CTAs/SM (smem ~105KB). Layer-0 x AND W0 both double-buffered via cp.async.
// Small-layer weights staged on demand into the same 32KB region.
// ---------------------------------------------------------------------------

namespace {

constexpr int REP      = 256;
constexpr int BW       = 64;
constexpr int TILE     = 128;
constexpr int NTHREADS = 256;    // tg = tid>>4 (16), cg = tid&15
constexpr int R        = 8;      // triplet rows: tg + 16*r
constexpr int ZS       = 68;     // padded row stride (floats); 272B, 16B-aligned

constexpr float PI_F   = 3.14159265358979323846f;
constexpr float EQ_STD = 0.1f;
constexpr float K_MEAN = 120.0f;
constexpr float K_STD  = 50.0f;

// smem layout (floats)
constexpr int OFF_R0   = 0;                      // x buf even / z0 / z2   (128*68)
constexpr int OFF_R1   = OFF_R0 + TILE * ZS;     // x buf odd  / z1 / z3
constexpr int OFF_W    = OFF_R1 + TILE * ZS;     // 2 x 4096: W0 half-chunks / small wts
constexpr int OFF_W4   = OFF_W + 2 * 4096;       // 128
constexpr int OFF_B0   = OFF_W4 + 128;
constexpr int OFF_B1   = OFF_B0 + 64;
constexpr int OFF_BSC  = OFF_B1 + 64;            // bs + b2
constexpr int OFF_B3   = OFF_BSC + 64;
constexpr int OFF_B4   = OFF_B3 + 64;            // 4
constexpr int OFF_IDX  = OFF_B4 + 4;             // TILE*3 ints
constexpr int SMEM_FLOATS = OFF_IDX + TILE * 3;
constexpr size_t SMEM_BYTES = (size_t)SMEM_FLOATS * sizeof(float);  // ~105 KB

__device__ __forceinline__ unsigned long long splat2(float x) {
    unsigned long long r;
    asm("mov.b64 %0, {%1, %1};" : "=l"(r) : "f"(x));
    return r;
}
__device__ __forceinline__ float2 unpack2(unsigned long long v) {
    float2 r;
    asm("mov.b64 {%0, %1}, %2;" : "=f"(r.x), "=f"(r.y) : "l"(v));
    return r;
}
#define FMA2(d, a, b) asm("fma.rn.f32x2 %0, %1, %2, %0;" : "+l"(d) : "l"(a), "l"(b))

__device__ __forceinline__ void cp16(float* dst_smem, const float* src) {
    unsigned sdst = (unsigned)__cvta_generic_to_shared(dst_smem);
    asm volatile("cp.async.cg.shared.global [%0], [%1], 16;" :: "r"(sdst), "l"(src));
}
__device__ __forceinline__ void cp_commit() {
    asm volatile("cp.async.commit_group;" ::: "memory");
}
__device__ __forceinline__ void cp_wait1() {
    asm volatile("cp.async.wait_group 1;" ::: "memory");
}
__device__ __forceinline__ void cp_wait0() {
    asm volatile("cp.async.wait_group 0;" ::: "memory");
}

__device__ __forceinline__ float eluf(float x) {
    return x > 0.0f ? x : expm1f(x);
}

// acc[2r],acc[2r+1]: cols cg4..cg4+3 for triplet row (tg + 16r).
// sact rows stride ZS (float4 reads); sw rows stride 64; 64 k-steps.
__device__ __forceinline__ void mm64(const float* __restrict__ sact,
                                     const float* __restrict__ sw,
                                     unsigned long long acc[2 * R],
                                     const int ltoff[R], int cg4) {
    #pragma unroll 1
    for (int k4 = 0; k4 < 16; k4++) {
        float4 xa[R];
        #pragma unroll
        for (int r = 0; r < R; r++)
            xa[r] = *(const float4*)(sact + ltoff[r] + k4 * 4);
        #pragma unroll
        for (int u = 0; u < 4; u++) {
            ulonglong2 w = *(const ulonglong2*)(sw + (k4 * 4 + u) * BW + cg4);
            #pragma unroll
            for (int r = 0; r < R; r++) {
                float xv = u == 0 ? xa[r].x : u == 1 ? xa[r].y : u == 2 ? xa[r].z : xa[r].w;
                unsigned long long s = splat2(xv);
                FMA2(acc[2 * r + 0], w.x, s);
                FMA2(acc[2 * r + 1], w.y, s);
            }
        }
    }
}

__device__ __forceinline__ void load_bias(const float* sb, int cg4,
                                          unsigned long long acc[2 * R]) {
    unsigned long long b0 = ((const unsigned long long*)(sb + cg4))[0];
    unsigned long long b1 = ((const unsigned long long*)(sb + cg4))[1];
    #pragma unroll
    for (int r = 0; r < R; r++) { acc[2 * r] = b0; acc[2 * r + 1] = b1; }
}

__device__ __forceinline__ void elu_store(float* dst, const int ltoff[R], int cg4,
                                          const unsigned long long acc[2 * R]) {
    #pragma unroll
    for (int r = 0; r < R; r++) {
        float2 p0 = unpack2(acc[2 * r]);
        float2 p1 = unpack2(acc[2 * r + 1]);
        *(float4*)(dst + ltoff[r] + cg4) =
            make_float4(eluf(p0.x), eluf(p0.y), eluf(p1.x), eluf(p1.y));
    }
}

__global__ void __launch_bounds__(NTHREADS, 2)
wap_kernel(const float* __restrict__ h,  const int* __restrict__ idxs,
           const float* __restrict__ W0, const float* __restrict__ b0,
           const float* __restrict__ Ws, const float* __restrict__ bs,
           const float* __restrict__ W1, const float* __restrict__ b1,
           const float* __restrict__ W2, const float* __restrict__ b2,
           const float* __restrict__ W3, const float* __restrict__ b3,
           const float* __restrict__ W4, const float* __restrict__ b4,
           float* __restrict__ out, int nT)
{
    extern __shared__ float smem[];
    float* sR0  = smem + OFF_R0;
    float* sR1  = smem + OFF_R1;
    float* sW   = smem + OFF_W;         // two 4096-float slots
    float* sW4  = smem + OFF_W4;
    float* sb0  = smem + OFF_B0;
    float* sb1  = smem + OFF_B1;
    float* sbsc = smem + OFF_BSC;
    float* sb3  = smem + OFF_B3;
    float* sb4  = smem + OFF_B4;
    int*   sidx = (int*)(smem + OFF_IDX);

    const int tid = threadIdx.x;
    const int cg4 = (tid & 15) * 4;
    const int tg  = tid >> 4;           // 0..15
    const int t0  = blockIdx.x * TILE;

    // ---- stage biases, W4, indices ----
    if (tid < 128) sW4[tid] = W4[tid];
    if (tid < 64) {
        sb0[tid] = b0[tid]; sb1[tid] = b1[tid];
        sbsc[tid] = bs[tid] + b2[tid]; sb3[tid] = b3[tid];
    }
    if (tid < 2) sb4[tid] = b4[tid];
    for (int i = tid; i < TILE * 3; i += NTHREADS) {
        int t = t0 + i / 3;
        if (t >= nT) t = nT - 1;        // clamp tail; extras computed, not stored
        sidx[i] = idxs[(size_t)t * 3 + (i % 3)];
    }
    __syncthreads();

    int ltoff[R];
    #pragma unroll
    for (int r = 0; r < R; r++) ltoff[r] = (tg + 16 * r) * ZS;

    float* Xbuf[2] = { sR0, sR1 };
    float* Wbuf[2] = { sW, sW + 4096 };
    const int myrowT = tid >> 1;        // triplet row this thread stages
    const int myhalf = (tid & 1) * 32;  // 32-float half of the 64-float sub-chunk

    // ---- layer 0: [768] -> [64]; 12 stages of (64 x-floats/row, 64 W0 rows) ----
    unsigned long long acc[2 * R];
    load_bias(sb0, cg4, acc);

    {   // prologue: stage s=0 (x sub-chunk + W0 half-chunk) as one group
        const float* xs = h + (size_t)sidx[myrowT * 3 + 0] * REP + myhalf;
        float* xd = Xbuf[0] + myrowT * ZS + myhalf;
        #pragma unroll
        for (int j = 0; j < 8; j++) cp16(xd + 4 * j, xs + 4 * j);
        const float* wsrc = W0 + tid * 16;
        float* wdst = Wbuf[0] + tid * 16;
        #pragma unroll
        for (int j = 0; j < 4; j++) cp16(wdst + 4 * j, wsrc + 4 * j);
        cp_commit();
    }

    for (int s = 0; s < 12; s++) {
        __syncthreads();                // mm64(s-1) done everywhere: buffers (s+1)&1 free
        if (s < 11) {
            const int n2 = (s + 1) >> 2, ks2 = (s + 1) & 3;
            const float* xs = h + (size_t)sidx[myrowT * 3 + n2] * REP + ks2 * 64 + myhalf;
            float* xd = Xbuf[(s + 1) & 1] + myrowT * ZS + myhalf;
            #pragma unroll
            for (int j = 0; j < 8; j++) cp16(xd + 4 * j, xs + 4 * j);
            const float* wsrc = W0 + (size_t)(s + 1) * 64 * BW + tid * 16;
            float* wdst = Wbuf[(s + 1) & 1] + tid * 16;
            #pragma unroll
            for (int j = 0; j < 4; j++) cp16(wdst + 4 * j, wsrc + 4 * j);
            cp_commit();
            cp_wait1();                 // stage s complete; s+1 in flight
        } else {
            cp_wait0();
        }
        __syncthreads();                // staged data visible to all
        mm64(Xbuf[s & 1], Wbuf[s & 1], acc, ltoff, cg4);
    }

    // z0 -> R0 (mm64(11) read R1 + Wbuf[1]; per-thread cells disjoint)
    elu_store(sR0, ltoff, cg4, acc);
    __syncthreads();                    // layer 0 fully done; W region free

    // ---- stage W1 -> slot0, Ws -> slot1 ----
    {
        const float* s1 = W1 + tid * 16;  float* d1 = Wbuf[0] + tid * 16;
        const float* s2 = Ws + tid * 16;  float* d2 = Wbuf[1] + tid * 16;
        #pragma unroll
        for (int j = 0; j < 4; j++) { cp16(d1 + 4 * j, s1 + 4 * j); cp16(d2 + 4 * j, s2 + 4 * j); }
        cp_commit(); cp_wait0();
    }
    __syncthreads();

    // ---- layer 1: z1 = elu(z0 @ W1 + b1) -> R1  (warp-local rows) ----
    load_bias(sb1, cg4, acc);
    mm64(sR0, Wbuf[0], acc, ltoff, cg4);
    elu_store(sR1, ltoff, cg4, acc);
    __syncthreads();                    // all W1 reads done -> slot0 reusable

    // prefetch W2 -> slot0, overlapped with the Ws mm64
    {
        const float* s2 = W2 + tid * 16;  float* d2 = Wbuf[0] + tid * 16;
        #pragma unroll
        for (int j = 0; j < 4; j++) cp16(d2 + 4 * j, s2 + 4 * j);
        cp_commit();
    }

    // ---- residual part A: acc = z0 @ Ws + (bs+b2) ----
    load_bias(sbsc, cg4, acc);
    mm64(sR0, Wbuf[1], acc, ltoff, cg4);
    cp_wait0();
    __syncthreads();                    // W2 staged + all Ws reads done -> slot1 reusable

    // prefetch W3 -> slot1, overlapped with the W2 mm64
    {
        const float* s3 = W3 + tid * 16;  float* d3 = Wbuf[1] + tid * 16;
        #pragma unroll
        for (int j = 0; j < 4; j++) cp16(d3 + 4 * j, s3 + 4 * j);
        cp_commit();
    }

    // ---- residual part B: acc += z1 @ W2; z2 = elu(acc) -> R0 ----
    mm64(sR1, Wbuf[0], acc, ltoff, cg4);
    elu_store(sR0, ltoff, cg4, acc);    // z0 reads finished in part A (pre-barrier)
    cp_wait0();
    __syncthreads();                    // W3 staged; z2 visible

    // ---- layer 3: z3 = elu(z2 @ W3 + b3) -> R1 ----
    load_bias(sb3, cg4, acc);
    mm64(sR0, Wbuf[1], acc, ltoff, cg4);
    elu_store(sR1, ltoff, cg4, acc);
    __syncthreads();                    // head reads cross-warp

    // ---- head: threads 0..127, one triplet each ----
    if (tid < TILE) {
        int t = t0 + tid;
        if (t < nT) {
            const float* zrow = sR1 + tid * ZS;
            float c0 = sb4[0], c1 = sb4[1];
            #pragma unroll
            for (int k4 = 0; k4 < 16; k4++) {
                float4 z4 = *(const float4*)(zrow + k4 * 4);
                float4 wA = *(const float4*)(sW4 + k4 * 8);
                float4 wB = *(const float4*)(sW4 + k4 * 8 + 4);
                c0 += z4.x * wA.x + z4.y * wA.z + z4.z * wB.x + z4.w * wB.z;
                c1 += z4.x * wA.y + z4.y * wA.w + z4.z * wB.y + z4.w * wB.w;
            }
            float eq = PI_F / (1.0f + expf(-c0 * (EQ_STD / PI_F)));
            float kk = K_STD * eluf(c1 + K_MEAN / K_STD);
            *(float2*)(out + (size_t)t * 2) = make_float2(eq, kk);
        }
    }
}

} // namespace

extern "C" void kernel_launch(void* const* d_in, const int* in_sizes, int n_in,
                              void* d_out, int out_size) {
    const float* h   = (const float*)d_in[0];
    const int*   idx = (const int*)  d_in[1];
    const float* W0  = (const float*)d_in[2];
    const float* b0  = (const float*)d_in[3];
    const float* Ws  = (const float*)d_in[4];
    const float* bs  = (const float*)d_in[5];
    const float* W1  = (const float*)d_in[6];
    const float* b1  = (const float*)d_in[7];
    const float* W2  = (const float*)d_in[8];
    const float* b2  = (const float*)d_in[9];
    const float* W3  = (const float*)d_in[10];
    const float* b3  = (const float*)d_in[11];
    const float* W4  = (const float*)d_in[12];
    const float* b4  = (const float*)d_in[13];
    float* out = (float*)d_out;

    int nT = in_sizes[1] / 3;
    int grid = (nT + TILE - 1) / TILE;

    cudaFuncSetAttribute(wap_kernel,
                         cudaFuncAttributeMaxDynamicSharedMemorySize,
                         (int)SMEM_BYTES);
    wap_kernel<<<grid, NTHREADS, SMEM_BYTES>>>(
        h, idx, W0, b0, Ws, bs, W1, b1, W2, b2, W3, b3, W4, b4, out, nT);
    (void)n_in; (void)out_size;
}

// round 5
// speedup vs baseline: 1.7456x; 1.1880x over previous
#include <cuda_runtime.h>
#include <math.h>

// ---------------------------------------------------------------------------
// WriteAngleParameters: triplet gather + MLP (fp32, packed f32x2 FMA)
// TILE=128, 256 threads (16 tg x 16 cg), R=8 triplets x 4 cols per thread.
// 2 CTAs/SM. Layer 0 uses a 3-deep cp.async pipeline (32-k stages, one
// __syncthreads per stage). Small layers warp-local, weights double-slotted.
// ---------------------------------------------------------------------------

namespace {

constexpr int REP      = 256;
constexpr int BW       = 64;
constexpr int TILE     = 128;
constexpr int NTHREADS = 256;     // tg = tid>>4 (16), cg = tid&15
constexpr int R        = 8;       // triplet rows: tg + 16*r
constexpr int ZS       = 68;      // z-row stride (floats); 272B, 16B-aligned
constexpr int XS       = 32;      // x-stage row stride (floats)
constexpr int NSTAGE   = 24;      // 768 k / 32

constexpr float PI_F   = 3.14159265358979323846f;
constexpr float EQ_STD = 0.1f;
constexpr float K_MEAN = 120.0f;
constexpr float K_STD  = 50.0f;

// smem layout (floats)
// Region A (12800): 3 x-stage bufs (3*4096) ; later z0/z2 (8704) + Wslot_a (4096)
// Region B (6144):  3 W-stage bufs (3*2048) ; later Wslot_b (4096)
// Region Z (8704):  z1/z3
constexpr int OFF_A    = 0;
constexpr int OFF_B    = OFF_A + 12800;
constexpr int OFF_Z    = OFF_B + 6144;
constexpr int OFF_W4   = OFF_Z + 8704;     // 128
constexpr int OFF_B0   = OFF_W4 + 128;
constexpr int OFF_B1   = OFF_B0 + 64;
constexpr int OFF_BSC  = OFF_B1 + 64;      // bs + b2
constexpr int OFF_B3   = OFF_BSC + 64;
constexpr int OFF_B4   = OFF_B3 + 64;      // 4
constexpr int SMEM_FLOATS = OFF_B4 + 4;
constexpr size_t SMEM_BYTES = (size_t)SMEM_FLOATS * sizeof(float);  // ~112.2 KB

constexpr int SLOT_A_OFF = 8704;           // inside region A

__device__ __forceinline__ unsigned long long splat2(float x) {
    unsigned long long r;
    asm("mov.b64 %0, {%1, %1};" : "=l"(r) : "f"(x));
    return r;
}
__device__ __forceinline__ float2 unpack2(unsigned long long v) {
    float2 r;
    asm("mov.b64 {%0, %1}, %2;" : "=f"(r.x), "=f"(r.y) : "l"(v));
    return r;
}
#define FMA2(d, a, b) asm("fma.rn.f32x2 %0, %1, %2, %0;" : "+l"(d) : "l"(a), "l"(b))

__device__ __forceinline__ void cp16(float* dst_smem, const float* src) {
    unsigned sdst = (unsigned)__cvta_generic_to_shared(dst_smem);
    asm volatile("cp.async.cg.shared.global [%0], [%1], 16;" :: "r"(sdst), "l"(src));
}
__device__ __forceinline__ void cp_commit() {
    asm volatile("cp.async.commit_group;" ::: "memory");
}
__device__ __forceinline__ void cp_wait1() {
    asm volatile("cp.async.wait_group 1;" ::: "memory");
}
__device__ __forceinline__ void cp_wait0() {
    asm volatile("cp.async.wait_group 0;" ::: "memory");
}

__device__ __forceinline__ float eluf(float x) {
    return x > 0.0f ? x : expm1f(x);
}

// 32 k-steps: act rows stride XS, weights stride 64.
__device__ __forceinline__ void mm32(const float* __restrict__ sact,
                                     const float* __restrict__ sw,
                                     unsigned long long acc[2 * R],
                                     int tg, int cg4) {
    #pragma unroll 1
    for (int k4 = 0; k4 < 8; k4++) {
        float4 xa[R];
        #pragma unroll
        for (int r = 0; r < R; r++)
            xa[r] = *(const float4*)(sact + (tg + 16 * r) * XS + k4 * 4);
        #pragma unroll
        for (int u = 0; u < 4; u++) {
            ulonglong2 w = *(const ulonglong2*)(sw + (k4 * 4 + u) * BW + cg4);
            #pragma unroll
            for (int r = 0; r < R; r++) {
                float xv = u == 0 ? xa[r].x : u == 1 ? xa[r].y : u == 2 ? xa[r].z : xa[r].w;
                unsigned long long s = splat2(xv);
                FMA2(acc[2 * r + 0], w.x, s);
                FMA2(acc[2 * r + 1], w.y, s);
            }
        }
    }
}

// 64 k-steps: act rows stride ZS, weights stride 64.
__device__ __forceinline__ void mm64z(const float* __restrict__ sact,
                                      const float* __restrict__ sw,
                                      unsigned long long acc[2 * R],
                                      const int ltoff[R], int cg4) {
    #pragma unroll 1
    for (int k4 = 0; k4 < 16; k4++) {
        float4 xa[R];
        #pragma unroll
        for (int r = 0; r < R; r++)
            xa[r] = *(const float4*)(sact + ltoff[r] + k4 * 4);
        #pragma unroll
        for (int u = 0; u < 4; u++) {
            ulonglong2 w = *(const ulonglong2*)(sw + (k4 * 4 + u) * BW + cg4);
            #pragma unroll
            for (int r = 0; r < R; r++) {
                float xv = u == 0 ? xa[r].x : u == 1 ? xa[r].y : u == 2 ? xa[r].z : xa[r].w;
                unsigned long long s = splat2(xv);
                FMA2(acc[2 * r + 0], w.x, s);
                FMA2(acc[2 * r + 1], w.y, s);
            }
        }
    }
}

__device__ __forceinline__ void load_bias(const float* sb, int cg4,
                                          unsigned long long acc[2 * R]) {
    unsigned long long b0 = ((const unsigned long long*)(sb + cg4))[0];
    unsigned long long b1 = ((const unsigned long long*)(sb + cg4))[1];
    #pragma unroll
    for (int r = 0; r < R; r++) { acc[2 * r] = b0; acc[2 * r + 1] = b1; }
}

__device__ __forceinline__ void elu_store(float* dst, const int ltoff[R], int cg4,
                                          const unsigned long long acc[2 * R]) {
    #pragma unroll
    for (int r = 0; r < R; r++) {
        float2 p0 = unpack2(acc[2 * r]);
        float2 p1 = unpack2(acc[2 * r + 1]);
        *(float4*)(dst + ltoff[r] + cg4) =
            make_float4(eluf(p0.x), eluf(p0.y), eluf(p1.x), eluf(p1.y));
    }
}

__global__ void __launch_bounds__(NTHREADS, 2)
wap_kernel(const float* __restrict__ h,  const int* __restrict__ idxs,
           const float* __restrict__ W0, const float* __restrict__ b0,
           const float* __restrict__ Ws, const float* __restrict__ bs,
           const float* __restrict__ W1, const float* __restrict__ b1,
           const float* __restrict__ W2, const float* __restrict__ b2,
           const float* __restrict__ W3, const float* __restrict__ b3,
           const float* __restrict__ W4, const float* __restrict__ b4,
           float* __restrict__ out, int nT)
{
    extern __shared__ float smem[];
    float* sA   = smem + OFF_A;          // x-stages / z0,z2 + Wslot_a
    float* sB   = smem + OFF_B;          // W-stages / Wslot_b
    float* sZ   = smem + OFF_Z;          // z1 / z3
    float* sW4  = smem + OFF_W4;
    float* sb0  = smem + OFF_B0;
    float* sb1  = smem + OFF_B1;
    float* sbsc = smem + OFF_BSC;
    float* sb3  = smem + OFF_B3;
    float* sb4  = smem + OFF_B4;

    float* slotA = sA + SLOT_A_OFF;      // 4096 floats
    float* slotB = sB;                   // 4096 floats

    const int tid = threadIdx.x;
    const int cg4 = (tid & 15) * 4;
    const int tg  = tid >> 4;            // 0..15
    const int t0  = blockIdx.x * TILE;

    // ---- my gather pointers (indices straight from gmem, no smem) ----
    const int myrow = tid >> 1;          // triplet row this thread stages
    const int myoff = (tid & 1) * 16;    // 16-float half of the 32-float sub-chunk
    int t_my = t0 + myrow;
    if (t_my >= nT) t_my = nT - 1;       // clamp tail; extras computed, not stored
    const float* xsrc0 = h + (size_t)idxs[3 * t_my + 0] * REP + myoff;
    const float* xsrc1 = h + (size_t)idxs[3 * t_my + 1] * REP + myoff;
    const float* xsrc2 = h + (size_t)idxs[3 * t_my + 2] * REP + myoff;

    // ---- stage biases / W4 ----
    if (tid < 128) sW4[tid] = W4[tid];
    if (tid < 64) {
        sb0[tid] = b0[tid]; sb1[tid] = b1[tid];
        sbsc[tid] = bs[tid] + b2[tid]; sb3[tid] = b3[tid];
    }
    if (tid < 2) sb4[tid] = b4[tid];

    // ---- prologue: issue stages 0 and 1 ----
    #pragma unroll
    for (int s = 0; s < 2; s++) {
        const float* xs = xsrc0 + s * 32;           // stage s < 8 -> node 0
        float* xd = sA + s * 4096 + myrow * XS + myoff;
        #pragma unroll
        for (int j = 0; j < 4; j++) cp16(xd + 4 * j, xs + 4 * j);
        const float* wsrc = W0 + (size_t)s * 2048 + tid * 8;
        float* wdst = sB + s * 2048 + tid * 8;
        cp16(wdst, wsrc); cp16(wdst + 4, wsrc + 4);
        cp_commit();
    }
    __syncthreads();                                 // biases visible (one-time)

    // ---- layer 0: 24 stages, one syncthreads each ----
    unsigned long long acc[2 * R];
    load_bias(sb0, cg4, acc);

    for (int s = 0; s < NSTAGE; s++) {
        if (s < NSTAGE - 2) cp_wait1(); else cp_wait0();   // stage s arrived
        __syncthreads();            // mm32(s-1) done everywhere; data visible
        if (s + 2 < NSTAGE) {       // prefetch stage s+2 into bufs (s+2)%3
            const int s2 = s + 2, n2 = s2 >> 3, ks2 = s2 & 7;
            const float* xs = (n2 == 0 ? xsrc0 : n2 == 1 ? xsrc1 : xsrc2) + ks2 * 32;
            float* xd = sA + (s2 % 3) * 4096 + myrow * XS + myoff;
            #pragma unroll
            for (int j = 0; j < 4; j++) cp16(xd + 4 * j, xs + 4 * j);
            const float* wsrc = W0 + (size_t)s2 * 2048 + tid * 8;
            float* wdst = sB + (s2 % 3) * 2048 + tid * 8;
            cp16(wdst, wsrc); cp16(wdst + 4, wsrc + 4);
            cp_commit();
        }
        mm32(sA + (s % 3) * 4096, sB + (s % 3) * 2048, acc, tg, cg4);
    }
    __syncthreads();                 // all warps done with mm32(23): A/B free

    int ltoff[R];
    #pragma unroll
    for (int r = 0; r < R; r++) ltoff[r] = (tg + 16 * r) * ZS;

    // z0 -> A[0] (stride ZS)
    elu_store(sA, ltoff, cg4, acc);

    // stage W1 -> slotA, Ws -> slotB (one group)
    {
        const float* s1 = W1 + tid * 16;  float* d1 = slotA + tid * 16;
        const float* s2 = Ws + tid * 16;  float* d2 = slotB + tid * 16;
        #pragma unroll
        for (int j = 0; j < 4; j++) { cp16(d1 + 4 * j, s1 + 4 * j); cp16(d2 + 4 * j, s2 + 4 * j); }
        cp_commit(); cp_wait0();
    }
    __syncthreads();                 // weights + z0 visible

    // ---- layer 1: z1 = elu(z0 @ W1 + b1) -> Z  (warp-local rows) ----
    load_bias(sb1, cg4, acc);
    mm64z(sA, slotA, acc, ltoff, cg4);
    elu_store(sZ, ltoff, cg4, acc);
    __syncthreads();                 // W1 reads done -> slotA reusable

    // prefetch W2 -> slotA under the Ws mm64
    {
        const float* s2 = W2 + tid * 16;  float* d2 = slotA + tid * 16;
        #pragma unroll
        for (int j = 0; j < 4; j++) cp16(d2 + 4 * j, s2 + 4 * j);
        cp_commit();
    }

    // ---- residual A: acc = z0 @ Ws + (bs+b2) ----
    load_bias(sbsc, cg4, acc);
    mm64z(sA, slotB, acc, ltoff, cg4);
    cp_wait0();
    __syncthreads();                 // W2 staged; Ws reads done -> slotB reusable

    // prefetch W3 -> slotB under the W2 mm64
    {
        const float* s3 = W3 + tid * 16;  float* d3 = slotB + tid * 16;
        #pragma unroll
        for (int j = 0; j < 4; j++) cp16(d3 + 4 * j, s3 + 4 * j);
        cp_commit();
    }

    // ---- residual B: acc += z1 @ W2; z2 = elu(acc) -> A (warp-local) ----
    mm64z(sZ, slotA, acc, ltoff, cg4);
    elu_store(sA, ltoff, cg4, acc);
    cp_wait0();
    __syncthreads();                 // W3 staged + visible

    // ---- layer 3: z3 = elu(z2 @ W3 + b3) -> Z ----
    load_bias(sb3, cg4, acc);
    mm64z(sA, slotB, acc, ltoff, cg4);
    elu_store(sZ, ltoff, cg4, acc);
    __syncthreads();                 // head reads cross-warp

    // ---- head: threads 0..127, one triplet each ----
    if (tid < TILE) {
        int t = t0 + tid;
        if (t < nT) {
            const float* zrow = sZ + tid * ZS;
            float c0 = sb4[0], c1 = sb4[1];
            #pragma unroll
            for (int k4 = 0; k4 < 16; k4++) {
                float4 z4 = *(const float4*)(zrow + k4 * 4);
                float4 wA = *(const float4*)(sW4 + k4 * 8);
                float4 wB = *(const float4*)(sW4 + k4 * 8 + 4);
                c0 += z4.x * wA.x + z4.y * wA.z + z4.z * wB.x + z4.w * wB.z;
                c1 += z4.x * wA.y + z4.y * wA.w + z4.z * wB.y + z4.w * wB.w;
            }
            float eq = PI_F / (1.0f + expf(-c0 * (EQ_STD / PI_F)));
            float kk = K_STD * eluf(c1 + K_MEAN / K_STD);
            *(float2*)(out + (size_t)t * 2) = make_float2(eq, kk);
        }
    }
}

} // namespace

extern "C" void kernel_launch(void* const* d_in, const int* in_sizes, int n_in,
                              void* d_out, int out_size) {
    const float* h   = (const float*)d_in[0];
    const int*   idx = (const int*)  d_in[1];
    const float* W0  = (const float*)d_in[2];
    const float* b0  = (const float*)d_in[3];
    const float* Ws  = (const float*)d_in[4];
    const float* bs  = (const float*)d_in[5];
    const float* W1  = (const float*)d_in[6];
    const float* b1  = (const float*)d_in[7];
    const float* W2  = (const float*)d_in[8];
    const float* b2  = (const float*)d_in[9];
    const float* W3  = (const float*)d_in[10];
    const float* b3  = (const float*)d_in[11];
    const float* W4  = (const float*)d_in[12];
    const float* b4  = (const float*)d_in[13];
    float* out = (float*)d_out;

    int nT = in_sizes[1] / 3;
    int grid = (nT + TILE - 1) / TILE;

    cudaFuncSetAttribute(wap_kernel,
                         cudaFuncAttributeMaxDynamicSharedMemorySize,
                         (int)SMEM_BYTES);
    wap_kernel<<<grid, NTHREADS, SMEM_BYTES>>>(
        h, idx, W0, b0, Ws, bs, W1, b1, W2, b2, W3, b3, W4, b4, out, nT);
    (void)n_in; (void)out_size;
}